// round 10
// baseline (speedup 1.0000x reference)
#include <cuda_runtime.h>

#define CC   32768
#define DD   1024
#define BB   16384
#define KEEP 0.95f
#define D4   (DD / 4)           // 256 float4 per row
#define ROWS 4                  // table rows per group
#define GMAIN (CC / ROWS)       // 8192 row-groups
#define CAP  16                 // slots per class (P(overflow) ~ 1e-18)
#define PERS 1184               // persistent blocks = 148 SMs x 8 (one wave)

// -------- static device scratch (zero-init at load; every run restores the
// zeroed state after consuming it -> graph-replay safe, no zeroing kernel) --
__device__ int   g_slotcnt[CC];       // arrival counters (reset by k_weights)
__device__ int   g_cnt[CC];           // clamped counts (overwritten each run)
__device__ float g_decay[CC];         // keep^count (overwritten each run)
__device__ int   g_idx[CC * CAP];     // slotted sample indices
__device__ float g_w[CC * CAP];       // slotted EMA weights
__device__ float g_bsum[PERS];
__device__ unsigned int g_done;       // reset by last k_main block

// 1) slot fill with inline dtype detection; probe and the always-in-bounds
//    int32 load issue concurrently (one DRAM trip in the common case).
//    Probe lanes [0,8192) as int64 (64 KB: in-bounds for int32[16384] (64 KB)
//    or int64[16384] (128 KB)). int32 data aliases "in range" only w.p.
//    ~2^-15 per lane -> detection certain across 256 lanes.
__global__ void k_fill(const void* __restrict__ cls_raw) {
    __shared__ int s_is32;
    const long long* c64 = (const long long*)cls_raw;
    const int*       c32 = (const int*)cls_raw;
    int th = threadIdx.x;
    int i  = blockIdx.x * 256 + th;
    if (th == 0) s_is32 = 0;
    __syncthreads();
    long long vp  = c64[i & 8191];          // probe; == c64[i] when i < 8192
    int       v32 = c32[i];                 // always in-bounds
    if (vp < 0 || vp >= CC) s_is32 = 1;     // benign race: same value
    __syncthreads();
    int c;
    if (s_is32)            c = v32;
    else if (i < 8192)     c = (int)vp;     // reuse the probe value
    else                   c = (int)c64[i]; // genuine int64 upper half
    int pos = atomicAdd(&g_slotcnt[c], 1);
    if (pos < CAP) g_idx[c * CAP + pos] = i;
}

// 2) per-class: sort slot indices ascending (recovers batch order), emit
//    weights + decay + clamped count; reset the arrival counter.
__global__ void k_weights() {
    int c = blockIdx.x * blockDim.x + threadIdx.x;
    if (c >= CC) return;
    int cnt = g_slotcnt[c];
    g_slotcnt[c] = 0;                          // restore zeroed state
    g_decay[c] = __powf(KEEP, (float)cnt);
    int m = cnt < CAP ? cnt : CAP;
    g_cnt[c] = m;
    if (m == 0) return;
    int slot = c * CAP;
    if (m == 1) {
        g_w[slot] = (1.0f - KEEP) * __powf(KEEP, (float)(cnt - 1));
        return;
    }
    int idx[CAP];
    for (int k = 0; k < m; k++) idx[k] = g_idx[slot + k];
    for (int a = 1; a < m; a++) {              // insertion sort ascending
        int v = idx[a];
        int b = a - 1;
        while (b >= 0 && idx[b] > v) { idx[b + 1] = idx[b]; b--; }
        idx[b + 1] = v;
    }
    for (int k = 0; k < m; k++) {
        g_idx[slot + k] = idx[k];
        g_w[slot + k]   = (1.0f - KEEP) * __powf(KEEP, (float)(cnt - 1 - k));
    }
}

// 3) persistent fused EMA + L1 + final reduction. One wave of 1184 blocks,
//    each striding over ~7 row-groups; inner body identical to the R5 winner.
__global__ void __launch_bounds__(256) k_main(const float4* __restrict__ s4,
                                              const float4* __restrict__ t4,
                                              const float4* __restrict__ l4,
                                              float* __restrict__ out) {
    int th = threadIdx.x;
    float p = 0.0f;

    for (int g = blockIdx.x; g < GMAIN; g += PERS) {
        int c0 = g * ROWS;

        // front-load: 8 independent vector loads + per-row scalars
        float4 sv[ROWS], tv[ROWS];
        float  dec[ROWS];
        int    cnt[ROWS];
        #pragma unroll
        for (int r = 0; r < ROWS; r++) {
            size_t base = (size_t)(c0 + r) * D4 + th;
            sv[r]  = s4[base];
            tv[r]  = t4[base];
            dec[r] = g_decay[c0 + r];
            cnt[r] = g_cnt[c0 + r];
        }

        #pragma unroll
        for (int r = 0; r < ROWS; r++) {
            float ax = sv[r].x * dec[r], ay = sv[r].y * dec[r];
            float az = sv[r].z * dec[r], aw = sv[r].w * dec[r];
            int slot = (c0 + r) * CAP;
            for (int k = 0; k < cnt[r]; k++) {
                int   i = __ldg(&g_idx[slot + k]);
                float w = __ldg(&g_w[slot + k]);
                float4 lv = l4[(size_t)i * D4 + th];
                ax += w * lv.x; ay += w * lv.y; az += w * lv.z; aw += w * lv.w;
            }
            p += fabsf(ax - tv[r].x) + fabsf(ay - tv[r].y)
               + fabsf(az - tv[r].z) + fabsf(aw - tv[r].w);
        }
    }

    // block reduce (fixed order -> deterministic)
    #pragma unroll
    for (int o = 16; o > 0; o >>= 1) p += __shfl_down_sync(0xffffffffu, p, o);
    __shared__ float sred[8];
    __shared__ bool  s_last;
    if ((th & 31) == 0) sred[th >> 5] = p;
    __syncthreads();
    if (th < 8) {
        float v = sred[th];
        #pragma unroll
        for (int o = 4; o > 0; o >>= 1) v += __shfl_down_sync(0xffu, v, o);
        if (th == 0) g_bsum[blockIdx.x] = v;
    }

    // last block: deterministic final reduction + g_done reset
    if (th == 0) {
        __threadfence();
        s_last = (atomicAdd(&g_done, 1u) == PERS - 1);
    }
    __syncthreads();
    if (s_last) {
        __threadfence();
        float s = 0.0f;
        for (int j = th; j < PERS; j += 256) s += g_bsum[j];   // fixed order
        #pragma unroll
        for (int o = 16; o > 0; o >>= 1) s += __shfl_down_sync(0xffffffffu, s, o);
        if ((th & 31) == 0) sred[th >> 5] = s;
        __syncthreads();
        if (th < 8) {
            float v = sred[th];
            #pragma unroll
            for (int o = 4; o > 0; o >>= 1) v += __shfl_down_sync(0xffu, v, o);
            if (th == 0) { out[0] = v / (float)CC; g_done = 0; }
        }
    }
}

extern "C" void kernel_launch(void* const* d_in, const int* in_sizes, int n_in,
                              void* d_out, int out_size) {
    const float* s   = (const float*)d_in[0];
    const float* t   = (const float*)d_in[1];
    const float* l   = (const float*)d_in[2];
    const void*  cls = d_in[3];
    float* out = (float*)d_out;

    k_fill<<<BB / 256, 256>>>(cls);
    k_weights<<<CC / 256, 256>>>();
    k_main<<<PERS, 256>>>((const float4*)s, (const float4*)t, (const float4*)l, out);
}

// round 11
// speedup vs baseline: 1.0264x; 1.0264x over previous
#include <cuda_runtime.h>

#define CC   32768
#define DD   1024
#define BB   16384
#define KEEP 0.95f
#define D4   (DD / 4)           // 256 float4 per row
#define ROWS 4                  // table rows per k_main block
#define GMAIN (CC / ROWS)       // 8192 blocks
#define CAP  16                 // slots per class (P(overflow) ~ 1e-18)

// -------- static device scratch (zero-init at load; every run restores the
// zeroed state after consuming it -> graph-replay safe, no zeroing kernel) --
__device__ int   g_slotcnt[CC];       // arrival counters (reset by k_weights)
__device__ int   g_cnt[CC];           // clamped counts (overwritten each run)
__device__ float g_decay[CC];         // keep^count (overwritten each run)
__device__ int   g_idx[CC * CAP];     // slotted sample indices
__device__ float g_w[CC * CAP];       // slotted EMA weights
__device__ float g_bsum[GMAIN];
__device__ unsigned int g_done;       // reset by last k_main block

// 1) slot fill with inline dtype detection; probe and the always-in-bounds
//    int32 load issue concurrently. Probe lanes [0,8192) as int64 (64 KB:
//    in-bounds for int32[16384] or int64[16384]); int32 data aliases to
//    "in range" only w.p. ~2^-15/lane -> detection certain over 256 lanes.
__global__ void k_fill(const void* __restrict__ cls_raw) {
    asm volatile("griddepcontrol.launch_dependents;");
    __shared__ int s_is32;
    const long long* c64 = (const long long*)cls_raw;
    const int*       c32 = (const int*)cls_raw;
    int th = threadIdx.x;
    int i  = blockIdx.x * 256 + th;
    if (th == 0) s_is32 = 0;
    __syncthreads();
    long long vp  = c64[i & 8191];          // probe; == c64[i] when i < 8192
    int       v32 = c32[i];                 // always in-bounds
    if (vp < 0 || vp >= CC) s_is32 = 1;     // benign race: same value
    __syncthreads();
    int c;
    if (s_is32)            c = v32;
    else if (i < 8192)     c = (int)vp;     // reuse the probe value
    else                   c = (int)c64[i]; // genuine int64 upper half
    int pos = atomicAdd(&g_slotcnt[c], 1);
    if (pos < CAP) g_idx[c * CAP + pos] = i;
}

// 2) per-class: sort slot indices ascending (recovers batch order), emit
//    weights + decay + clamped count; reset the arrival counter.
//    PDL: blocks launch while k_fill drains; wait before touching its output.
__global__ void k_weights() {
    asm volatile("griddepcontrol.launch_dependents;");
    asm volatile("griddepcontrol.wait;" ::: "memory");
    int c = blockIdx.x * blockDim.x + threadIdx.x;
    if (c >= CC) return;
    int cnt = g_slotcnt[c];
    g_slotcnt[c] = 0;                          // restore zeroed state
    g_decay[c] = __powf(KEEP, (float)cnt);
    int m = cnt < CAP ? cnt : CAP;
    g_cnt[c] = m;
    if (m == 0) return;
    int slot = c * CAP;
    if (m == 1) {
        g_w[slot] = (1.0f - KEEP) * __powf(KEEP, (float)(cnt - 1));
        return;
    }
    int idx[CAP];
    for (int k = 0; k < m; k++) idx[k] = g_idx[slot + k];
    for (int a = 1; a < m; a++) {              // insertion sort ascending
        int v = idx[a];
        int b = a - 1;
        while (b >= 0 && idx[b] > v) { idx[b + 1] = idx[b]; b--; }
        idx[b + 1] = v;
    }
    for (int k = 0; k < m; k++) {
        g_idx[slot + k] = idx[k];
        g_w[slot + k]   = (1.0f - KEEP) * __powf(KEEP, (float)(cnt - 1 - k));
    }
}

// 3) fused EMA + L1 + final reduction (R5/R7 winner body). PDL: the 8 s/t
//    vector loads (aux-independent, 256 MB of the 320 MB total) issue BEFORE
//    griddepcontrol.wait, hiding the aux chain under memory latency.
__global__ void __launch_bounds__(256) k_main(const float4* __restrict__ s4,
                                              const float4* __restrict__ t4,
                                              const float4* __restrict__ l4,
                                              float* __restrict__ out) {
    int c0 = blockIdx.x * ROWS;
    int th = threadIdx.x;

    // pre-wait prefetch: 8 independent vector loads from harness inputs
    float4 sv[ROWS], tv[ROWS];
    #pragma unroll
    for (int r = 0; r < ROWS; r++) {
        size_t base = (size_t)(c0 + r) * D4 + th;
        sv[r] = s4[base];
        tv[r] = t4[base];
    }

    asm volatile("griddepcontrol.wait;" ::: "memory");

    float  dec[ROWS];
    int    cnt[ROWS];
    #pragma unroll
    for (int r = 0; r < ROWS; r++) {
        dec[r] = g_decay[c0 + r];
        cnt[r] = g_cnt[c0 + r];
    }

    float p = 0.0f;
    #pragma unroll
    for (int r = 0; r < ROWS; r++) {
        float ax = sv[r].x * dec[r], ay = sv[r].y * dec[r];
        float az = sv[r].z * dec[r], aw = sv[r].w * dec[r];
        int slot = (c0 + r) * CAP;
        for (int k = 0; k < cnt[r]; k++) {
            int   i = __ldg(&g_idx[slot + k]);
            float w = __ldg(&g_w[slot + k]);
            float4 lv = l4[(size_t)i * D4 + th];
            ax += w * lv.x; ay += w * lv.y; az += w * lv.z; aw += w * lv.w;
        }
        p += fabsf(ax - tv[r].x) + fabsf(ay - tv[r].y)
           + fabsf(az - tv[r].z) + fabsf(aw - tv[r].w);
    }

    // block reduce (fixed order -> deterministic)
    #pragma unroll
    for (int o = 16; o > 0; o >>= 1) p += __shfl_down_sync(0xffffffffu, p, o);
    __shared__ float sred[8];
    __shared__ bool  s_last;
    if ((th & 31) == 0) sred[th >> 5] = p;
    __syncthreads();
    if (th < 8) {
        float v = sred[th];
        #pragma unroll
        for (int o = 4; o > 0; o >>= 1) v += __shfl_down_sync(0xffu, v, o);
        if (th == 0) g_bsum[blockIdx.x] = v;
    }

    // last block: deterministic final reduction + g_done reset
    if (th == 0) {
        __threadfence();
        s_last = (atomicAdd(&g_done, 1u) == GMAIN - 1);
    }
    __syncthreads();
    if (s_last) {
        __threadfence();
        float s = 0.0f;
        const float4* b4 = (const float4*)g_bsum;
        #pragma unroll
        for (int j = 0; j < GMAIN / 1024; j++) {          // 8 float4 each
            float4 x = b4[th * (GMAIN / 1024) + j];
            s += x.x + x.y + x.z + x.w;
        }
        #pragma unroll
        for (int o = 16; o > 0; o >>= 1) s += __shfl_down_sync(0xffffffffu, s, o);
        if ((th & 31) == 0) sred[th >> 5] = s;
        __syncthreads();
        if (th < 8) {
            float v = sred[th];
            #pragma unroll
            for (int o = 4; o > 0; o >>= 1) v += __shfl_down_sync(0xffu, v, o);
            if (th == 0) { out[0] = v / (float)CC; g_done = 0; }
        }
    }
}

extern "C" void kernel_launch(void* const* d_in, const int* in_sizes, int n_in,
                              void* d_out, int out_size) {
    const float* s   = (const float*)d_in[0];
    const float* t   = (const float*)d_in[1];
    const float* l   = (const float*)d_in[2];
    const void*  cls = d_in[3];
    float* out = (float*)d_out;

    // primary: plain launch
    k_fill<<<BB / 256, 256>>>(cls);

    // dependents: programmatic stream serialization (PDL)
    cudaLaunchAttribute attr[1];
    attr[0].id = cudaLaunchAttributeProgrammaticStreamSerialization;
    attr[0].val.programmaticStreamSerializationAllowed = 1;

    {
        cudaLaunchConfig_t cfg = {};
        cfg.gridDim = dim3(CC / 256);
        cfg.blockDim = dim3(256);
        cfg.attrs = attr;
        cfg.numAttrs = 1;
        cudaLaunchKernelEx(&cfg, k_weights);
    }
    {
        cudaLaunchConfig_t cfg = {};
        cfg.gridDim = dim3(GMAIN);
        cfg.blockDim = dim3(256);
        cfg.attrs = attr;
        cfg.numAttrs = 1;
        cudaLaunchKernelEx(&cfg, k_main,
                           (const float4*)s, (const float4*)t,
                           (const float4*)l, out);
    }
}

// round 12
// speedup vs baseline: 1.1810x; 1.1506x over previous
#include <cuda_runtime.h>

#define CC   32768
#define DD   1024
#define BB   16384
#define KEEP 0.95f
#define D4   (DD / 4)           // 256 float4 per row
#define ROWS 4                  // table rows per k_main block
#define GMAIN (CC / ROWS)       // 8192 blocks
#define CAP  16                 // slots per class (P(overflow) ~ 1e-18)

// -------- static device scratch (zero-init at load; every run restores the
// zeroed state after consuming it -> graph-replay safe, no zeroing kernel) --
__device__ int   g_slotcnt[CC];       // arrival counters (reset by k_weights)
__device__ int   g_cnt[CC];           // clamped counts (overwritten each run)
__device__ float g_decay[CC];         // keep^count (overwritten each run)
__device__ int   g_idx[CC * CAP];     // slotted sample indices
__device__ float g_w[CC * CAP];       // slotted EMA weights
__device__ float g_bsum[GMAIN];
__device__ unsigned int g_done;       // reset by last k_main block

// 1) slot fill with inline dtype detection; probe and the always-in-bounds
//    int32 load issue concurrently (one DRAM trip in the common case).
//    Probe lanes [0,8192) as int64 (64 KB: in-bounds for int32[16384] (64 KB)
//    or int64[16384] (128 KB)); int32 data aliases to "in range" only w.p.
//    ~2^-15 per lane -> detection certain over 256 lanes.
__global__ void k_fill(const void* __restrict__ cls_raw) {
    __shared__ int s_is32;
    const long long* c64 = (const long long*)cls_raw;
    const int*       c32 = (const int*)cls_raw;
    int th = threadIdx.x;
    int i  = blockIdx.x * 256 + th;
    if (th == 0) s_is32 = 0;
    __syncthreads();
    long long vp  = c64[i & 8191];          // probe; == c64[i] when i < 8192
    int       v32 = c32[i];                 // always in-bounds
    if (vp < 0 || vp >= CC) s_is32 = 1;     // benign race: same value
    __syncthreads();
    int c;
    if (s_is32)            c = v32;
    else if (i < 8192)     c = (int)vp;     // reuse the probe value
    else                   c = (int)c64[i]; // genuine int64 upper half
    int pos = atomicAdd(&g_slotcnt[c], 1);
    if (pos < CAP) g_idx[c * CAP + pos] = i;
}

// 2) per-class: sort slot indices ascending (recovers batch order), emit
//    weights + decay + clamped count; reset the arrival counter.
__global__ void k_weights() {
    int c = blockIdx.x * blockDim.x + threadIdx.x;
    if (c >= CC) return;
    int cnt = g_slotcnt[c];
    g_slotcnt[c] = 0;                          // restore zeroed state
    g_decay[c] = __powf(KEEP, (float)cnt);
    int m = cnt < CAP ? cnt : CAP;
    g_cnt[c] = m;
    if (m == 0) return;
    int slot = c * CAP;
    if (m == 1) {
        g_w[slot] = (1.0f - KEEP) * __powf(KEEP, (float)(cnt - 1));
        return;
    }
    int idx[CAP];
    for (int k = 0; k < m; k++) idx[k] = g_idx[slot + k];
    for (int a = 1; a < m; a++) {              // insertion sort ascending
        int v = idx[a];
        int b = a - 1;
        while (b >= 0 && idx[b] > v) { idx[b + 1] = idx[b]; b--; }
        idx[b + 1] = v;
    }
    for (int k = 0; k < m; k++) {
        g_idx[slot + k] = idx[k];
        g_w[slot + k]   = (1.0f - KEEP) * __powf(KEEP, (float)(cnt - 1 - k));
    }
}

// 3) fused EMA + L1 + final reduction: 4 table rows per block (R5/R7 winner)
__global__ void __launch_bounds__(256) k_main(const float4* __restrict__ s4,
                                              const float4* __restrict__ t4,
                                              const float4* __restrict__ l4,
                                              float* __restrict__ out) {
    int c0 = blockIdx.x * ROWS;
    int th = threadIdx.x;

    // front-load: 8 independent vector loads + per-row scalars
    float4 sv[ROWS], tv[ROWS];
    float  dec[ROWS];
    int    cnt[ROWS];
    #pragma unroll
    for (int r = 0; r < ROWS; r++) {
        size_t base = (size_t)(c0 + r) * D4 + th;
        sv[r]  = s4[base];
        tv[r]  = t4[base];
        dec[r] = g_decay[c0 + r];
        cnt[r] = g_cnt[c0 + r];
    }

    float p = 0.0f;
    #pragma unroll
    for (int r = 0; r < ROWS; r++) {
        float ax = sv[r].x * dec[r], ay = sv[r].y * dec[r];
        float az = sv[r].z * dec[r], aw = sv[r].w * dec[r];
        int slot = (c0 + r) * CAP;
        for (int k = 0; k < cnt[r]; k++) {
            int   i = __ldg(&g_idx[slot + k]);
            float w = __ldg(&g_w[slot + k]);
            float4 lv = l4[(size_t)i * D4 + th];
            ax += w * lv.x; ay += w * lv.y; az += w * lv.z; aw += w * lv.w;
        }
        p += fabsf(ax - tv[r].x) + fabsf(ay - tv[r].y)
           + fabsf(az - tv[r].z) + fabsf(aw - tv[r].w);
    }

    // block reduce (fixed order -> deterministic)
    #pragma unroll
    for (int o = 16; o > 0; o >>= 1) p += __shfl_down_sync(0xffffffffu, p, o);
    __shared__ float sred[8];
    __shared__ bool  s_last;
    if ((th & 31) == 0) sred[th >> 5] = p;
    __syncthreads();
    if (th < 8) {
        float v = sred[th];
        #pragma unroll
        for (int o = 4; o > 0; o >>= 1) v += __shfl_down_sync(0xffu, v, o);
        if (th == 0) g_bsum[blockIdx.x] = v;
    }

    // last block: deterministic final reduction + g_done reset
    if (th == 0) {
        __threadfence();
        s_last = (atomicAdd(&g_done, 1u) == GMAIN - 1);
    }
    __syncthreads();
    if (s_last) {
        __threadfence();
        float s = 0.0f;
        const float4* b4 = (const float4*)g_bsum;
        #pragma unroll
        for (int j = 0; j < GMAIN / 1024; j++) {          // 8 float4 each
            float4 x = b4[th * (GMAIN / 1024) + j];
            s += x.x + x.y + x.z + x.w;
        }
        #pragma unroll
        for (int o = 16; o > 0; o >>= 1) s += __shfl_down_sync(0xffffffffu, s, o);
        if ((th & 31) == 0) sred[th >> 5] = s;
        __syncthreads();
        if (th < 8) {
            float v = sred[th];
            #pragma unroll
            for (int o = 4; o > 0; o >>= 1) v += __shfl_down_sync(0xffu, v, o);
            if (th == 0) { out[0] = v / (float)CC; g_done = 0; }
        }
    }
}

extern "C" void kernel_launch(void* const* d_in, const int* in_sizes, int n_in,
                              void* d_out, int out_size) {
    const float* s   = (const float*)d_in[0];
    const float* t   = (const float*)d_in[1];
    const float* l   = (const float*)d_in[2];
    const void*  cls = d_in[3];
    float* out = (float*)d_out;

    k_fill<<<BB / 256, 256>>>(cls);
    k_weights<<<CC / 256, 256>>>();
    k_main<<<GMAIN, 256>>>((const float4*)s, (const float4*)t, (const float4*)l, out);
}

// round 14
// speedup vs baseline: 1.1919x; 1.0093x over previous
#include <cuda_runtime.h>

#define CC   32768
#define DD   1024
#define BB   16384
#define KEEP 0.95f
#define D4   (DD / 4)           // 256 float4 per row
#define ROWS 4                  // table rows per k_main block
#define GMAIN (CC / ROWS)       // 8192 blocks
#define CAP  16                 // slots per class (P(overflow) ~ 1e-18)

// -------- static device scratch (zero-init at load; every run restores the
// zeroed state after consuming it -> graph-replay safe, no zeroing kernel) --
__device__ int   g_slotcnt[CC];       // arrival counters (reset by k_weights)
__device__ int   g_cnt[CC];           // clamped counts (overwritten each run)
__device__ float g_decay[CC];         // keep^count (overwritten each run)
__device__ int   g_idx[CC * CAP];     // slotted sample indices
__device__ float g_w[CC * CAP];       // slotted EMA weights
__device__ float g_bsum[GMAIN];
__device__ unsigned int g_done;       // reset by last k_main block

// 1) slot fill, warp-ballot dtype detection (no block barrier, one DRAM epoch).
//    Probe lanes [0,8192) as int64 (64 KB: in-bounds for int32[16384] (64 KB)
//    or int64[16384] (128 KB)). If the data is int32, a fused pair reads
//    "in range" only w.p. ~2^-15; P(all 32 warp lanes alias) ~ 2^-480 -> the
//    warp-consensus is as certain as a block-wide one, minus the barrier.
__global__ void k_fill(const void* __restrict__ cls_raw) {
    const long long* c64 = (const long long*)cls_raw;
    const int*       c32 = (const int*)cls_raw;
    int i = blockIdx.x * 128 + threadIdx.x;
    long long vp  = c64[i & 8191];          // probe; == c64[i] when i < 8192
    int       v32 = c32[i];                 // always in-bounds, issues with probe
    int bad = (vp < 0 || vp >= CC);
    int is32 = __any_sync(0xffffffffu, bad);
    int c;
    if (is32)              c = v32;
    else if (i < 8192)     c = (int)vp;     // reuse the probe value
    else                   c = (int)c64[i]; // genuine int64 upper half
    int pos = atomicAdd(&g_slotcnt[c], 1);
    if (pos < CAP) g_idx[c * CAP + pos] = i;
}

// 2) per-class: sort slot indices ascending (recovers batch order), emit
//    weights + decay + clamped count; reset the arrival counter.
__global__ void k_weights() {
    int c = blockIdx.x * blockDim.x + threadIdx.x;
    if (c >= CC) return;
    int cnt = g_slotcnt[c];
    g_slotcnt[c] = 0;                          // restore zeroed state
    g_decay[c] = __powf(KEEP, (float)cnt);
    int m = cnt < CAP ? cnt : CAP;
    g_cnt[c] = m;
    if (m == 0) return;
    int slot = c * CAP;
    if (m == 1) {
        g_w[slot] = (1.0f - KEEP) * __powf(KEEP, (float)(cnt - 1));
        return;
    }
    int idx[CAP];
    for (int k = 0; k < m; k++) idx[k] = g_idx[slot + k];
    for (int a = 1; a < m; a++) {              // insertion sort ascending
        int v = idx[a];
        int b = a - 1;
        while (b >= 0 && idx[b] > v) { idx[b + 1] = idx[b]; b--; }
        idx[b + 1] = v;
    }
    for (int k = 0; k < m; k++) {
        g_idx[slot + k] = idx[k];
        g_w[slot + k]   = (1.0f - KEEP) * __powf(KEEP, (float)(cnt - 1 - k));
    }
}

// 3) fused EMA + L1 + final reduction: 4 table rows per block (R5/R7 winner,
//    byte-identical)
__global__ void __launch_bounds__(256) k_main(const float4* __restrict__ s4,
                                              const float4* __restrict__ t4,
                                              const float4* __restrict__ l4,
                                              float* __restrict__ out) {
    int c0 = blockIdx.x * ROWS;
    int th = threadIdx.x;

    // front-load: 8 independent vector loads + per-row scalars
    float4 sv[ROWS], tv[ROWS];
    float  dec[ROWS];
    int    cnt[ROWS];
    #pragma unroll
    for (int r = 0; r < ROWS; r++) {
        size_t base = (size_t)(c0 + r) * D4 + th;
        sv[r]  = s4[base];
        tv[r]  = t4[base];
        dec[r] = g_decay[c0 + r];
        cnt[r] = g_cnt[c0 + r];
    }

    float p = 0.0f;
    #pragma unroll
    for (int r = 0; r < ROWS; r++) {
        float ax = sv[r].x * dec[r], ay = sv[r].y * dec[r];
        float az = sv[r].z * dec[r], aw = sv[r].w * dec[r];
        int slot = (c0 + r) * CAP;
        for (int k = 0; k < cnt[r]; k++) {
            int   i = __ldg(&g_idx[slot + k]);
            float w = __ldg(&g_w[slot + k]);
            float4 lv = l4[(size_t)i * D4 + th];
            ax += w * lv.x; ay += w * lv.y; az += w * lv.z; aw += w * lv.w;
        }
        p += fabsf(ax - tv[r].x) + fabsf(ay - tv[r].y)
           + fabsf(az - tv[r].z) + fabsf(aw - tv[r].w);
    }

    // block reduce (fixed order -> deterministic)
    #pragma unroll
    for (int o = 16; o > 0; o >>= 1) p += __shfl_down_sync(0xffffffffu, p, o);
    __shared__ float sred[8];
    __shared__ bool  s_last;
    if ((th & 31) == 0) sred[th >> 5] = p;
    __syncthreads();
    if (th < 8) {
        float v = sred[th];
        #pragma unroll
        for (int o = 4; o > 0; o >>= 1) v += __shfl_down_sync(0xffu, v, o);
        if (th == 0) g_bsum[blockIdx.x] = v;
    }

    // last block: deterministic final reduction + g_done reset
    if (th == 0) {
        __threadfence();
        s_last = (atomicAdd(&g_done, 1u) == GMAIN - 1);
    }
    __syncthreads();
    if (s_last) {
        __threadfence();
        float s = 0.0f;
        const float4* b4 = (const float4*)g_bsum;
        #pragma unroll
        for (int j = 0; j < GMAIN / 1024; j++) {          // 8 float4 each
            float4 x = b4[th * (GMAIN / 1024) + j];
            s += x.x + x.y + x.z + x.w;
        }
        #pragma unroll
        for (int o = 16; o > 0; o >>= 1) s += __shfl_down_sync(0xffffffffu, s, o);
        if ((th & 31) == 0) sred[th >> 5] = s;
        __syncthreads();
        if (th < 8) {
            float v = sred[th];
            #pragma unroll
            for (int o = 4; o > 0; o >>= 1) v += __shfl_down_sync(0xffu, v, o);
            if (th == 0) { out[0] = v / (float)CC; g_done = 0; }
        }
    }
}

extern "C" void kernel_launch(void* const* d_in, const int* in_sizes, int n_in,
                              void* d_out, int out_size) {
    const float* s   = (const float*)d_in[0];
    const float* t   = (const float*)d_in[1];
    const float* l   = (const float*)d_in[2];
    const void*  cls = d_in[3];
    float* out = (float*)d_out;

    k_fill<<<BB / 128, 128>>>(cls);
    k_weights<<<CC / 256, 256>>>();
    k_main<<<GMAIN, 256>>>((const float4*)s, (const float4*)t, (const float4*)l, out);
}

// round 15
// speedup vs baseline: 1.2229x; 1.0260x over previous
#include <cuda_runtime.h>

#define CC   32768
#define DD   1024
#define BB   16384
#define KEEP 0.95f
#define D4   (DD / 4)           // 256 float4 per row
#define ROWS 4                  // table rows per k_main block
#define GMAIN (CC / ROWS)       // 8192 blocks
#define CAP  16                 // slots per class (P(overflow) ~ 1e-18)

// -------- static device scratch (zero-init at load; every run restores the
// zeroed state after consuming it -> graph-replay safe, no zeroing kernel) --
__device__ int   g_slotcnt[CC];       // arrival counters (reset by k_weights)
__device__ int   g_cnt[CC];           // clamped counts (overwritten each run)
__device__ float g_decay[CC];         // keep^count (overwritten each run)
__device__ int   g_idx[CC * CAP];     // slotted sample indices
__device__ float g_w[CC * CAP];       // slotted EMA weights
__device__ float g_bsum[GMAIN];
__device__ unsigned int g_done;       // reset by last k_main block

// 1) slot fill, warp-ballot dtype detection (one DRAM epoch).
//    Probe lanes [0,8192) as int64 (64 KB: in-bounds for int32[16384] (64 KB)
//    or int64[16384] (128 KB)). int32 data aliases "in range" only w.p.
//    ~2^-15/lane; P(all 32 warp lanes alias) ~ 2^-480 -> certain detection.
//    PDL primary: fire dependent (k_weights) block spin-up immediately; its
//    griddepcontrol.wait still orders all our stores before its reads.
__global__ void k_fill(const void* __restrict__ cls_raw) {
    asm volatile("griddepcontrol.launch_dependents;");
    const long long* c64 = (const long long*)cls_raw;
    const int*       c32 = (const int*)cls_raw;
    int i = blockIdx.x * 128 + threadIdx.x;
    long long vp  = c64[i & 8191];          // probe; == c64[i] when i < 8192
    int       v32 = c32[i];                 // always in-bounds, issues with probe
    int bad = (vp < 0 || vp >= CC);
    int is32 = __any_sync(0xffffffffu, bad);
    int c;
    if (is32)              c = v32;
    else if (i < 8192)     c = (int)vp;     // reuse the probe value
    else                   c = (int)c64[i]; // genuine int64 upper half
    int pos = atomicAdd(&g_slotcnt[c], 1);
    if (pos < CAP) g_idx[c * CAP + pos] = i;
}

// 2) per-class: sort slot indices ascending (recovers batch order), emit
//    weights + decay + clamped count; reset the arrival counter.
//    PDL dependent: blocks spin up while k_fill drains; wait before reads.
__global__ void k_weights() {
    asm volatile("griddepcontrol.wait;" ::: "memory");
    int c = blockIdx.x * blockDim.x + threadIdx.x;
    if (c >= CC) return;
    int cnt = g_slotcnt[c];
    g_slotcnt[c] = 0;                          // restore zeroed state
    g_decay[c] = __powf(KEEP, (float)cnt);
    int m = cnt < CAP ? cnt : CAP;
    g_cnt[c] = m;
    if (m == 0) return;
    int slot = c * CAP;
    if (m == 1) {
        g_w[slot] = (1.0f - KEEP) * __powf(KEEP, (float)(cnt - 1));
        return;
    }
    int idx[CAP];
    for (int k = 0; k < m; k++) idx[k] = g_idx[slot + k];
    for (int a = 1; a < m; a++) {              // insertion sort ascending
        int v = idx[a];
        int b = a - 1;
        while (b >= 0 && idx[b] > v) { idx[b + 1] = idx[b]; b--; }
        idx[b + 1] = v;
    }
    for (int k = 0; k < m; k++) {
        g_idx[slot + k] = idx[k];
        g_w[slot + k]   = (1.0f - KEEP) * __powf(KEEP, (float)(cnt - 1 - k));
    }
}

// 3) fused EMA + L1 + final reduction: 4 table rows per block (R5/R7 winner,
//    byte-identical; plain launch, no PDL)
__global__ void __launch_bounds__(256) k_main(const float4* __restrict__ s4,
                                              const float4* __restrict__ t4,
                                              const float4* __restrict__ l4,
                                              float* __restrict__ out) {
    int c0 = blockIdx.x * ROWS;
    int th = threadIdx.x;

    // front-load: 8 independent vector loads + per-row scalars
    float4 sv[ROWS], tv[ROWS];
    float  dec[ROWS];
    int    cnt[ROWS];
    #pragma unroll
    for (int r = 0; r < ROWS; r++) {
        size_t base = (size_t)(c0 + r) * D4 + th;
        sv[r]  = s4[base];
        tv[r]  = t4[base];
        dec[r] = g_decay[c0 + r];
        cnt[r] = g_cnt[c0 + r];
    }

    float p = 0.0f;
    #pragma unroll
    for (int r = 0; r < ROWS; r++) {
        float ax = sv[r].x * dec[r], ay = sv[r].y * dec[r];
        float az = sv[r].z * dec[r], aw = sv[r].w * dec[r];
        int slot = (c0 + r) * CAP;
        for (int k = 0; k < cnt[r]; k++) {
            int   i = __ldg(&g_idx[slot + k]);
            float w = __ldg(&g_w[slot + k]);
            float4 lv = l4[(size_t)i * D4 + th];
            ax += w * lv.x; ay += w * lv.y; az += w * lv.z; aw += w * lv.w;
        }
        p += fabsf(ax - tv[r].x) + fabsf(ay - tv[r].y)
           + fabsf(az - tv[r].z) + fabsf(aw - tv[r].w);
    }

    // block reduce (fixed order -> deterministic)
    #pragma unroll
    for (int o = 16; o > 0; o >>= 1) p += __shfl_down_sync(0xffffffffu, p, o);
    __shared__ float sred[8];
    __shared__ bool  s_last;
    if ((th & 31) == 0) sred[th >> 5] = p;
    __syncthreads();
    if (th < 8) {
        float v = sred[th];
        #pragma unroll
        for (int o = 4; o > 0; o >>= 1) v += __shfl_down_sync(0xffu, v, o);
        if (th == 0) g_bsum[blockIdx.x] = v;
    }

    // last block: deterministic final reduction + g_done reset
    if (th == 0) {
        __threadfence();
        s_last = (atomicAdd(&g_done, 1u) == GMAIN - 1);
    }
    __syncthreads();
    if (s_last) {
        __threadfence();
        float s = 0.0f;
        const float4* b4 = (const float4*)g_bsum;
        #pragma unroll
        for (int j = 0; j < GMAIN / 1024; j++) {          // 8 float4 each
            float4 x = b4[th * (GMAIN / 1024) + j];
            s += x.x + x.y + x.z + x.w;
        }
        #pragma unroll
        for (int o = 16; o > 0; o >>= 1) s += __shfl_down_sync(0xffffffffu, s, o);
        if ((th & 31) == 0) sred[th >> 5] = s;
        __syncthreads();
        if (th < 8) {
            float v = sred[th];
            #pragma unroll
            for (int o = 4; o > 0; o >>= 1) v += __shfl_down_sync(0xffu, v, o);
            if (th == 0) { out[0] = v / (float)CC; g_done = 0; }
        }
    }
}

extern "C" void kernel_launch(void* const* d_in, const int* in_sizes, int n_in,
                              void* d_out, int out_size) {
    const float* s   = (const float*)d_in[0];
    const float* t   = (const float*)d_in[1];
    const float* l   = (const float*)d_in[2];
    const void*  cls = d_in[3];
    float* out = (float*)d_out;

    k_fill<<<BB / 128, 128>>>(cls);

    // k_weights as PDL dependent of k_fill only
    cudaLaunchAttribute attr[1];
    attr[0].id = cudaLaunchAttributeProgrammaticStreamSerialization;
    attr[0].val.programmaticStreamSerializationAllowed = 1;
    cudaLaunchConfig_t cfg = {};
    cfg.gridDim = dim3(CC / 128);
    cfg.blockDim = dim3(128);
    cfg.attrs = attr;
    cfg.numAttrs = 1;
    cudaLaunchKernelEx(&cfg, k_weights);

    // k_main: plain launch, serializes behind k_weights as usual
    k_main<<<GMAIN, 256>>>((const float4*)s, (const float4*)t, (const float4*)l, out);
}